// round 9
// baseline (speedup 1.0000x reference)
#include <cuda_runtime.h>
#include <cuda_fp16.h>
#include <cstdint>

// Problem dims
#define B_ROWS 8192
#define KDIM   4096
#define NDIM   4096
#define CAPQ   492

// GEMM tiling (fp16 operands, fp32 accum)
// CTA 128x256, 8 warps as 2(M) x 4(N), warp tile 64x64 (square -> min ldsm traffic)
#define BM 128
#define BN 256
#define BK 64                          // 64 halves = 128 B rows
#define STAGES 3
#define MT (B_ROWS / BM)               // 64
#define NT (NDIM / BN)                 // 16
#define KT (KDIM / BK)                 // 64
#define A_BYTES (BM * BK * 2)          // 16384
#define B_BYTES (BN * BK * 2)          // 32768
#define STAGE_BYTES (A_BYTES + B_BYTES)     // 49152
#define SMEM_SIZE (STAGES * STAGE_BYTES)    // 147456 -> 1 CTA/SM

// Scratch (allocations forbidden -> __device__ globals)
__device__ __half g_Wh[(size_t)NDIM * KDIM];   // half W, [n][k]
__device__ __half g_xh[(size_t)B_ROWS * KDIM]; // half x, [m][k]

// ------------------------------------------------------------ fused prep ----
#define CVT_BLOCKS 2048
__global__ __launch_bounds__(256)
void prep_kernel(const float* __restrict__ values, const int* __restrict__ col,
                 const float4* __restrict__ x) {
    __shared__ float row[KDIM];
    const int tid = threadIdx.x;

    if (blockIdx.x < NDIM) {
        const int o = blockIdx.x;
        float4* r4 = (float4*)row;
        #pragma unroll
        for (int i = 0; i < KDIM / 4 / 256; i++)
            r4[i * 256 + tid] = make_float4(0.f, 0.f, 0.f, 0.f);
        __syncthreads();

        const float* v = values + (size_t)o * CAPQ;
        const int*   c = col    + (size_t)o * CAPQ;
        for (int s = tid; s < CAPQ; s += 256) {
            float val = v[s];
            if (val != 0.0f) atomicAdd(&row[c[s]], val);
        }
        __syncthreads();

        __half2* out = (__half2*)(g_Wh + (size_t)o * KDIM);
        #pragma unroll
        for (int i = 0; i < KDIM / 4 / 256; i++) {
            float4 f = r4[i * 256 + tid];
            int j = (i * 256 + tid) * 2;
            out[j]     = __floats2half2_rn(f.x, f.y);
            out[j + 1] = __floats2half2_rn(f.z, f.w);
        }
    } else {
        const size_t n4 = (size_t)B_ROWS * KDIM / 4;
        __half2* out = (__half2*)g_xh;
        for (size_t i = (size_t)(blockIdx.x - NDIM) * 256 + tid; i < n4;
             i += (size_t)CVT_BLOCKS * 256) {
            float4 v = x[i];
            out[i * 2]     = __floats2half2_rn(v.x, v.y);
            out[i * 2 + 1] = __floats2half2_rn(v.z, v.w);
        }
    }
}

// --------------------------------------------------------------- GEMM kernel -
// 256 threads = 8 warps in 2(M) x 4(N); warp tile 64x64; mma.m16n8k16 f16->f32.
// 3-stage cp.async; fragment double-buffering; 144KB smem -> 1 CTA/SM.
// Smem traffic: 128KB ldsm + 48KB sts per 2048-cyc stage = 86 B/cyc < 128 cap.
__global__ __launch_bounds__(256, 1)
void gemm_kernel(const float* __restrict__ bias, float* __restrict__ y)
{
    extern __shared__ __align__(128) unsigned char smem[];
    const uint32_t sbase = (uint32_t)__cvta_generic_to_shared(smem);
    const int tid  = threadIdx.x;
    const int lane = tid & 31;
    const int wid  = tid >> 5;
    const int wm   = wid & 1;      // 2 M groups of 64
    const int wn   = wid >> 1;     // 4 N groups of 64

    const int m0 = (blockIdx.x / NT) * BM;
    const int n0 = (blockIdx.x % NT) * BN;

    const __half* Ag = g_xh + (size_t)m0 * KDIM;
    const __half* Bg = g_Wh + (size_t)n0 * KDIM;

    auto load_stage = [&](int kt, int slot) {
        const uint32_t sa = sbase + slot * STAGE_BYTES;
        const uint32_t sb = sa + A_BYTES;
        const __half* ga = Ag + kt * BK;
        const __half* gb = Bg + kt * BK;
        #pragma unroll
        for (int i = 0; i < 4; i++) {            // A: 1024 16B chunks
            int chunk = i * 256 + tid;
            int r = chunk >> 3, c = chunk & 7;
            uint32_t so = sa + r * 128 + ((c ^ (r & 7)) << 4);
            const __half* g = ga + (size_t)r * KDIM + c * 8;
            asm volatile("cp.async.cg.shared.global [%0], [%1], 16;" :: "r"(so), "l"(g));
        }
        #pragma unroll
        for (int i = 0; i < 8; i++) {            // B: 2048 16B chunks
            int chunk = i * 256 + tid;
            int r = chunk >> 3, c = chunk & 7;
            uint32_t so = sb + r * 128 + ((c ^ (r & 7)) << 4);
            const __half* g = gb + (size_t)r * KDIM + c * 8;
            asm volatile("cp.async.cg.shared.global [%0], [%1], 16;" :: "r"(so), "l"(g));
        }
        asm volatile("cp.async.commit_group;" ::: "memory");
    };

    float acc[4][8][4];
    #pragma unroll
    for (int i = 0; i < 4; i++)
        #pragma unroll
        for (int j = 0; j < 8; j++)
            #pragma unroll
            for (int k = 0; k < 4; k++) acc[i][j][k] = 0.f;

    const int br_base = wn * 64 + ((lane >> 4) << 3) + (lane & 7);   // + q*16
    const int bc_sel  = (lane >> 3) & 1;                             // + 2*ks
    const int ar_base = wm * 64 + (lane & 15);                       // + mt*16
    const int ac_sel  = lane >> 4;                                   // + 2*ks

    auto compute_stage = [&](int slot) {
        const uint32_t sa = sbase + slot * STAGE_BYTES;
        const uint32_t sb = sa + A_BYTES;

        uint32_t bf[2][16];  // B frags (n64 = 4 q-groups), double-buffered over ks
        uint32_t af[2][4];   // A frags, double-buffered over mt

        auto ldB = [&](int ks, uint32_t* dst) {
            #pragma unroll
            for (int q = 0; q < 4; q++) {
                int r = br_base + q * 16;
                int c = 2 * ks + bc_sel;
                uint32_t addr = sb + r * 128 + ((c ^ (r & 7)) << 4);
                asm volatile("ldmatrix.sync.aligned.m8n8.x4.shared.b16 {%0,%1,%2,%3}, [%4];"
                    : "=r"(dst[q*4+0]), "=r"(dst[q*4+1]), "=r"(dst[q*4+2]), "=r"(dst[q*4+3])
                    : "r"(addr));
            }
        };
        auto ldA = [&](int ks, int mt, uint32_t* dst) {
            int r = ar_base + mt * 16;
            int c = 2 * ks + ac_sel;
            uint32_t addr = sa + r * 128 + ((c ^ (r & 7)) << 4);
            asm volatile("ldmatrix.sync.aligned.m8n8.x4.shared.b16 {%0,%1,%2,%3}, [%4];"
                : "=r"(dst[0]), "=r"(dst[1]), "=r"(dst[2]), "=r"(dst[3])
                : "r"(addr));
        };

        ldB(0, bf[0]);
        ldA(0, 0, af[0]);

        #pragma unroll
        for (int ks = 0; ks < 4; ks++) {
            if (ks < 3) ldB(ks + 1, bf[(ks + 1) & 1]);
            const uint32_t* b = bf[ks & 1];
            #pragma unroll
            for (int mt = 0; mt < 4; mt++) {
                if (mt < 3)      ldA(ks,     mt + 1, af[(mt + 1) & 1]);
                else if (ks < 3) ldA(ks + 1, 0,      af[0]);
                const uint32_t* a = af[mt & 1];
                #pragma unroll
                for (int nt = 0; nt < 8; nt++) {
                    asm volatile(
                        "mma.sync.aligned.m16n8k16.row.col.f32.f16.f16.f32 "
                        "{%0,%1,%2,%3},{%4,%5,%6,%7},{%8,%9},{%0,%1,%2,%3};"
                        : "+f"(acc[mt][nt][0]), "+f"(acc[mt][nt][1]),
                          "+f"(acc[mt][nt][2]), "+f"(acc[mt][nt][3])
                        : "r"(a[0]), "r"(a[1]), "r"(a[2]), "r"(a[3]),
                          "r"(b[(nt >> 1) * 4 + (nt & 1) * 2]),
                          "r"(b[(nt >> 1) * 4 + (nt & 1) * 2 + 1]));
                }
            }
        }
    };

    load_stage(0, 0);
    load_stage(1, 1);

    int slot = 0, nslot = 2;
    for (int kt = 0; kt < KT - 2; kt++) {
        asm volatile("cp.async.wait_group 1;" ::: "memory");
        __syncthreads();
        load_stage(kt + 2, nslot);
        compute_stage(slot);
        if (++slot == 3) slot = 0;
        if (++nslot == 3) nslot = 0;
    }
    asm volatile("cp.async.wait_group 1;" ::: "memory");
    __syncthreads();
    compute_stage(slot);
    if (++slot == 3) slot = 0;
    asm volatile("cp.async.wait_group 0;" ::: "memory");
    __syncthreads();
    compute_stage(slot);

    // ---- epilogue ----
    const int g   = lane >> 2;
    const int tig = lane & 3;
    #pragma unroll
    for (int mt = 0; mt < 4; mt++) {
        const int row = m0 + wm * 64 + mt * 16 + g;
        #pragma unroll
        for (int nt = 0; nt < 8; nt++) {
            const int col = n0 + wn * 64 + nt * 8 + tig * 2;
            const float b0 = __ldg(bias + col), b1 = __ldg(bias + col + 1);
            float2 v0 = make_float2(acc[mt][nt][0] + b0, acc[mt][nt][1] + b1);
            float2 v1 = make_float2(acc[mt][nt][2] + b0, acc[mt][nt][3] + b1);
            *reinterpret_cast<float2*>(y + (size_t)row       * NDIM + col) = v0;
            *reinterpret_cast<float2*>(y + (size_t)(row + 8) * NDIM + col) = v1;
        }
    }
}

// ------------------------------------------------------------------- host ----
extern "C" void kernel_launch(void* const* d_in, const int* in_sizes, int n_in,
                              void* d_out, int out_size) {
    const float* x      = (const float*)d_in[0];
    const float* values = (const float*)d_in[1];
    const int*   col    = (const int*)d_in[2];
    const float* bias   = (const float*)d_in[3];
    float* y = (float*)d_out;

    prep_kernel<<<NDIM + CVT_BLOCKS, 256>>>(values, col, (const float4*)x);

    static bool attr_set = false;
    if (!attr_set) {
        cudaFuncSetAttribute(gemm_kernel, cudaFuncAttributeMaxDynamicSharedMemorySize, SMEM_SIZE);
        attr_set = true;
    }
    gemm_kernel<<<MT * NT, 256, SMEM_SIZE>>>(bias, y);
}

// round 11
// speedup vs baseline: 1.1106x; 1.1106x over previous
#include <cuda_runtime.h>
#include <cuda_fp16.h>
#include <cstdint>

// Problem dims
#define B_ROWS 8192
#define KDIM   4096
#define NDIM   4096
#define CAPQ   492

// GEMM tiling (fp16 operands, fp32 accum) — R6/R8 proven geometry
#define BM 128
#define BN 128
#define BK 64                          // 64 halves = 128 B rows
#define STAGES 3
#define MT (B_ROWS / BM)               // 64
#define NT (NDIM / BN)                 // 32
#define KT (KDIM / BK)                 // 64
#define A_BYTES (BM * BK * 2)          // 16384
#define B_BYTES (BN * BK * 2)          // 16384
#define STAGE_BYTES (A_BYTES + B_BYTES)
#define SMEM_SIZE (128 + STAGES * STAGE_BYTES)   // mbarriers + tiles; 2 CTAs/SM

// Scratch (allocations forbidden -> __device__ globals)
__device__ __half g_Wh[(size_t)NDIM * KDIM];   // half W, [n][k]
__device__ __half g_xh[(size_t)B_ROWS * KDIM]; // half x, [m][k]

// ----------------------------------------------------------- mbarrier utils -
__device__ __forceinline__ void mbar_init(uint32_t a, uint32_t cnt) {
    asm volatile("mbarrier.init.shared.b64 [%0], %1;" :: "r"(a), "r"(cnt) : "memory");
}
__device__ __forceinline__ void mbar_arrive(uint32_t a) {
    asm volatile("mbarrier.arrive.shared.b64 _, [%0];" :: "r"(a) : "memory");
}
__device__ __forceinline__ void cpasync_mbar_arrive(uint32_t a) {
    // .noinc is load-bearing: the default form pre-increments the expected
    // count (net-zero progress) and deadlocks a count=nthreads barrier.
    asm volatile("cp.async.mbarrier.arrive.noinc.shared.b64 [%0];" :: "r"(a) : "memory");
}
__device__ __forceinline__ void mbar_wait(uint32_t a, uint32_t parity) {
    uint32_t done;
    asm volatile(
        "{\n\t.reg .pred p;\n\t"
        "mbarrier.try_wait.parity.shared.b64 p, [%1], %2;\n\t"
        "selp.b32 %0, 1, 0, p;\n\t}"
        : "=r"(done) : "r"(a), "r"(parity) : "memory");
    while (!done) {
        asm volatile(
            "{\n\t.reg .pred p;\n\t"
            "mbarrier.try_wait.parity.shared.b64 p, [%1], %2, 0x989680;\n\t"
            "selp.b32 %0, 1, 0, p;\n\t}"
            : "=r"(done) : "r"(a), "r"(parity) : "memory");
    }
    asm volatile("fence.acquire.cta;" ::: "memory");
}

// ------------------------------------------------------------ fused prep ----
#define CVT_BLOCKS 2048
__global__ __launch_bounds__(256)
void prep_kernel(const float* __restrict__ values, const int* __restrict__ col,
                 const float4* __restrict__ x) {
    __shared__ float row[KDIM];
    const int tid = threadIdx.x;

    if (blockIdx.x < NDIM) {
        const int o = blockIdx.x;
        float4* r4 = (float4*)row;
        #pragma unroll
        for (int i = 0; i < KDIM / 4 / 256; i++)
            r4[i * 256 + tid] = make_float4(0.f, 0.f, 0.f, 0.f);
        __syncthreads();

        const float* v = values + (size_t)o * CAPQ;
        const int*   c = col    + (size_t)o * CAPQ;
        for (int s = tid; s < CAPQ; s += 256) {
            float val = v[s];
            if (val != 0.0f) atomicAdd(&row[c[s]], val);
        }
        __syncthreads();

        __half2* out = (__half2*)(g_Wh + (size_t)o * KDIM);
        #pragma unroll
        for (int i = 0; i < KDIM / 4 / 256; i++) {
            float4 f = r4[i * 256 + tid];
            int j = (i * 256 + tid) * 2;
            out[j]     = __floats2half2_rn(f.x, f.y);
            out[j + 1] = __floats2half2_rn(f.z, f.w);
        }
    } else {
        const size_t n4 = (size_t)B_ROWS * KDIM / 4;
        __half2* out = (__half2*)g_xh;
        for (size_t i = (size_t)(blockIdx.x - NDIM) * 256 + tid; i < n4;
             i += (size_t)CVT_BLOCKS * 256) {
            float4 v = x[i];
            out[i * 2]     = __floats2half2_rn(v.x, v.y);
            out[i * 2 + 1] = __floats2half2_rn(v.z, v.w);
        }
    }
}

// --------------------------------------------------------------- GEMM kernel -
// 256 threads = 8 warps in 2(M) x 4(N); warp tile 64x32; mma.m16n8k16 f16->f32.
// 3-stage cp.async pipeline with per-stage mbarrier full/empty pairs (no
// CTA-wide __syncthreads in the mainloop): warps drift to absorb crossbar
// queuing. full count=256 (cp.async.mbarrier.arrive.noinc per thread),
// empty count=8 (lane0 per warp after last read of the slot).
__global__ __launch_bounds__(256, 2)
void gemm_kernel(const float* __restrict__ bias, float* __restrict__ y)
{
    extern __shared__ __align__(128) unsigned char smem[];
    const uint32_t sbase = (uint32_t)__cvta_generic_to_shared(smem);
    const uint32_t tiles = sbase + 128;
    const int tid  = threadIdx.x;
    const int lane = tid & 31;
    const int wid  = tid >> 5;
    const int wm   = wid & 1;      // 2 M groups of 64
    const int wn   = wid >> 1;     // 4 N groups of 32

    // mbarriers: full[s] = sbase + s*16, empty[s] = sbase + s*16 + 8
    if (tid == 0) {
        #pragma unroll
        for (int s = 0; s < STAGES; s++) {
            mbar_init(sbase + s * 16,     256);  // full
            mbar_init(sbase + s * 16 + 8,   8);  // empty
        }
    }
    __syncthreads();

    const int m0 = (blockIdx.x / NT) * BM;
    const int n0 = (blockIdx.x % NT) * BN;

    const __half* Ag = g_xh + (size_t)m0 * KDIM;
    const __half* Bg = g_Wh + (size_t)n0 * KDIM;

    auto load_stage = [&](int kt, int slot) {
        const uint32_t sa = tiles + slot * STAGE_BYTES;
        const uint32_t sb = sa + A_BYTES;
        const __half* ga = Ag + kt * BK;
        const __half* gb = Bg + kt * BK;
        #pragma unroll
        for (int i = 0; i < 4; i++) {
            int chunk = i * 256 + tid;
            int r = chunk >> 3, c = chunk & 7;
            uint32_t so = sa + r * 128 + ((c ^ (r & 7)) << 4);
            const __half* g = ga + (size_t)r * KDIM + c * 8;
            asm volatile("cp.async.cg.shared.global [%0], [%1], 16;" :: "r"(so), "l"(g));
        }
        #pragma unroll
        for (int i = 0; i < 4; i++) {
            int chunk = i * 256 + tid;
            int r = chunk >> 3, c = chunk & 7;
            uint32_t so = sb + r * 128 + ((c ^ (r & 7)) << 4);
            const __half* g = gb + (size_t)r * KDIM + c * 8;
            asm volatile("cp.async.cg.shared.global [%0], [%1], 16;" :: "r"(so), "l"(g));
        }
        // arrives on full[slot] once this thread's copies complete (.noinc)
        cpasync_mbar_arrive(sbase + slot * 16);
    };

    float acc[4][4][4];
    #pragma unroll
    for (int i = 0; i < 4; i++)
        #pragma unroll
        for (int j = 0; j < 4; j++)
            #pragma unroll
            for (int k = 0; k < 4; k++) acc[i][j][k] = 0.f;

    const int br_base = wn * 32 + ((lane >> 4) << 3) + (lane & 7);   // + q*16
    const int bc_sel  = (lane >> 3) & 1;                             // + 2*ks
    const int ar_base = wm * 64 + (lane & 15);                       // + mt*16
    const int ac_sel  = lane >> 4;                                   // + 2*ks

    auto compute_stage = [&](int slot) {
        const uint32_t sa = tiles + slot * STAGE_BYTES;
        const uint32_t sb = sa + A_BYTES;

        uint32_t bf[2][8];
        uint32_t af[2][4];

        auto ldB = [&](int ks, uint32_t* dst) {
            #pragma unroll
            for (int q = 0; q < 2; q++) {
                int r = br_base + q * 16;
                int c = 2 * ks + bc_sel;
                uint32_t addr = sb + r * 128 + ((c ^ (r & 7)) << 4);
                asm volatile("ldmatrix.sync.aligned.m8n8.x4.shared.b16 {%0,%1,%2,%3}, [%4];"
                    : "=r"(dst[q*4+0]), "=r"(dst[q*4+1]), "=r"(dst[q*4+2]), "=r"(dst[q*4+3])
                    : "r"(addr));
            }
        };
        auto ldA = [&](int ks, int mt, uint32_t* dst) {
            int r = ar_base + mt * 16;
            int c = 2 * ks + ac_sel;
            uint32_t addr = sa + r * 128 + ((c ^ (r & 7)) << 4);
            asm volatile("ldmatrix.sync.aligned.m8n8.x4.shared.b16 {%0,%1,%2,%3}, [%4];"
                : "=r"(dst[0]), "=r"(dst[1]), "=r"(dst[2]), "=r"(dst[3])
                : "r"(addr));
        };

        ldB(0, bf[0]);
        ldA(0, 0, af[0]);

        #pragma unroll
        for (int ks = 0; ks < 4; ks++) {
            if (ks < 3) ldB(ks + 1, bf[(ks + 1) & 1]);
            const uint32_t* b = bf[ks & 1];
            #pragma unroll
            for (int mt = 0; mt < 4; mt++) {
                if (mt < 3)      ldA(ks,     mt + 1, af[(mt + 1) & 1]);
                else if (ks < 3) ldA(ks + 1, 0,      af[0]);
                const uint32_t* a = af[mt & 1];
                #pragma unroll
                for (int nt = 0; nt < 4; nt++) {
                    asm volatile(
                        "mma.sync.aligned.m16n8k16.row.col.f32.f16.f16.f32 "
                        "{%0,%1,%2,%3},{%4,%5,%6,%7},{%8,%9},{%0,%1,%2,%3};"
                        : "+f"(acc[mt][nt][0]), "+f"(acc[mt][nt][1]),
                          "+f"(acc[mt][nt][2]), "+f"(acc[mt][nt][3])
                        : "r"(a[0]), "r"(a[1]), "r"(a[2]), "r"(a[3]),
                          "r"(b[(nt >> 1) * 4 + (nt & 1) * 2]),
                          "r"(b[(nt >> 1) * 4 + (nt & 1) * 2 + 1]));
                }
            }
        }
    };

    // prologue: stages 0 and 1 (empty-wait not needed on first use)
    load_stage(0, 0);
    load_stage(1, 1);

    for (int kt = 0; kt < KT; kt++) {
        const int ls = kt + 2;
        if (ls < KT) {
            const int s = ls % 3;
            if (ls >= 3)
                mbar_wait(sbase + s * 16 + 8, ((ls / 3) - 1) & 1);   // empty[s]
            load_stage(ls, s);
        }
        const int cs = kt % 3;
        mbar_wait(sbase + cs * 16, (kt / 3) & 1);                    // full[cs]
        compute_stage(cs);
        __syncwarp();
        if (lane == 0) mbar_arrive(sbase + cs * 16 + 8);             // empty[cs]
    }

    // ---- epilogue ----
    const int g   = lane >> 2;
    const int tig = lane & 3;
    #pragma unroll
    for (int mt = 0; mt < 4; mt++) {
        const int row = m0 + wm * 64 + mt * 16 + g;
        #pragma unroll
        for (int nt = 0; nt < 4; nt++) {
            const int col = n0 + wn * 32 + nt * 8 + tig * 2;
            const float b0 = __ldg(bias + col), b1 = __ldg(bias + col + 1);
            float2 v0 = make_float2(acc[mt][nt][0] + b0, acc[mt][nt][1] + b1);
            float2 v1 = make_float2(acc[mt][nt][2] + b0, acc[mt][nt][3] + b1);
            *reinterpret_cast<float2*>(y + (size_t)row       * NDIM + col) = v0;
            *reinterpret_cast<float2*>(y + (size_t)(row + 8) * NDIM + col) = v1;
        }
    }
}

// ------------------------------------------------------------------- host ----
extern "C" void kernel_launch(void* const* d_in, const int* in_sizes, int n_in,
                              void* d_out, int out_size) {
    const float* x      = (const float*)d_in[0];
    const float* values = (const float*)d_in[1];
    const int*   col    = (const int*)d_in[2];
    const float* bias   = (const float*)d_in[3];
    float* y = (float*)d_out;

    prep_kernel<<<NDIM + CVT_BLOCKS, 256>>>(values, col, (const float4*)x);

    static bool attr_set = false;
    if (!attr_set) {
        cudaFuncSetAttribute(gemm_kernel, cudaFuncAttributeMaxDynamicSharedMemorySize, SMEM_SIZE);
        attr_set = true;
    }
    gemm_kernel<<<MT * NT, 256, SMEM_SIZE>>>(bias, y);
}

// round 12
// speedup vs baseline: 1.1634x; 1.0476x over previous
#include <cuda_runtime.h>
#include <cuda_fp16.h>
#include <cstdint>

// Problem dims
#define B_ROWS 8192
#define KDIM   4096
#define NDIM   4096
#define CAPQ   492

// GEMM tiling: CTA 128x256, 8 warps as 2(M) x 4(N), warp tile 64x64.
// 1 CTA/SM (regs ~190), 4-stage cp.async + mbarrier pipeline (196KB smem).
#define BM 128
#define BN 256
#define BK 64                          // 64 halves = 128 B rows
#define STAGES 4
#define MT (B_ROWS / BM)               // 64
#define NT (NDIM / BN)                 // 16
#define KT (KDIM / BK)                 // 64
#define A_BYTES (BM * BK * 2)          // 16384
#define B_BYTES (BN * BK * 2)          // 32768
#define STAGE_BYTES (A_BYTES + B_BYTES)      // 49152
#define SMEM_SIZE (128 + STAGES * STAGE_BYTES)   // 196736

// Scratch (allocations forbidden -> __device__ globals)
__device__ __half g_Wh[(size_t)NDIM * KDIM];   // half W, [n][k]
__device__ __half g_xh[(size_t)B_ROWS * KDIM]; // half x, [m][k]

// ----------------------------------------------------------- mbarrier utils -
__device__ __forceinline__ void mbar_init(uint32_t a, uint32_t cnt) {
    asm volatile("mbarrier.init.shared.b64 [%0], %1;" :: "r"(a), "r"(cnt) : "memory");
}
__device__ __forceinline__ void mbar_arrive(uint32_t a) {
    asm volatile("mbarrier.arrive.shared.b64 _, [%0];" :: "r"(a) : "memory");
}
__device__ __forceinline__ void cpasync_mbar_arrive(uint32_t a) {
    // .noinc is load-bearing (default form pre-increments expected count -> hang)
    asm volatile("cp.async.mbarrier.arrive.noinc.shared.b64 [%0];" :: "r"(a) : "memory");
}
__device__ __forceinline__ void mbar_wait(uint32_t a, uint32_t parity) {
    uint32_t done;
    asm volatile(
        "{\n\t.reg .pred p;\n\t"
        "mbarrier.try_wait.parity.shared.b64 p, [%1], %2;\n\t"
        "selp.b32 %0, 1, 0, p;\n\t}"
        : "=r"(done) : "r"(a), "r"(parity) : "memory");
    while (!done) {
        asm volatile(
            "{\n\t.reg .pred p;\n\t"
            "mbarrier.try_wait.parity.shared.b64 p, [%1], %2, 0x989680;\n\t"
            "selp.b32 %0, 1, 0, p;\n\t}"
            : "=r"(done) : "r"(a), "r"(parity) : "memory");
    }
    asm volatile("fence.acquire.cta;" ::: "memory");
}

// ------------------------------------------------------------ fused prep ----
#define CVT_BLOCKS 2048
__global__ __launch_bounds__(256)
void prep_kernel(const float* __restrict__ values, const int* __restrict__ col,
                 const float4* __restrict__ x) {
    __shared__ float row[KDIM];
    const int tid = threadIdx.x;

    if (blockIdx.x < NDIM) {
        const int o = blockIdx.x;
        float4* r4 = (float4*)row;
        #pragma unroll
        for (int i = 0; i < KDIM / 4 / 256; i++)
            r4[i * 256 + tid] = make_float4(0.f, 0.f, 0.f, 0.f);
        __syncthreads();

        const float* v = values + (size_t)o * CAPQ;
        const int*   c = col    + (size_t)o * CAPQ;
        for (int s = tid; s < CAPQ; s += 256) {
            float val = v[s];
            if (val != 0.0f) atomicAdd(&row[c[s]], val);
        }
        __syncthreads();

        __half2* out = (__half2*)(g_Wh + (size_t)o * KDIM);
        #pragma unroll
        for (int i = 0; i < KDIM / 4 / 256; i++) {
            float4 f = r4[i * 256 + tid];
            int j = (i * 256 + tid) * 2;
            out[j]     = __floats2half2_rn(f.x, f.y);
            out[j + 1] = __floats2half2_rn(f.z, f.w);
        }
    } else {
        const size_t n4 = (size_t)B_ROWS * KDIM / 4;
        __half2* out = (__half2*)g_xh;
        for (size_t i = (size_t)(blockIdx.x - NDIM) * 256 + tid; i < n4;
             i += (size_t)CVT_BLOCKS * 256) {
            float4 v = x[i];
            out[i * 2]     = __floats2half2_rn(v.x, v.y);
            out[i * 2 + 1] = __floats2half2_rn(v.z, v.w);
        }
    }
}

// --------------------------------------------------------------- GEMM kernel -
// 256 threads = 8 warps in 2(M) x 4(N); warp tile 64x64; mma.m16n8k16 f16->f32.
// 4-stage cp.async pipeline with per-stage mbarrier full/empty pairs; no
// CTA-wide barrier in the mainloop, so the 2 warps/SMSP drift independently.
// Smem demand ~88 B/cyc at full tensor rate (30% crossbar headroom).
__global__ __launch_bounds__(256, 1)
void gemm_kernel(const float* __restrict__ bias, float* __restrict__ y)
{
    extern __shared__ __align__(128) unsigned char smem[];
    const uint32_t sbase = (uint32_t)__cvta_generic_to_shared(smem);
    const uint32_t tiles = sbase + 128;
    const int tid  = threadIdx.x;
    const int lane = tid & 31;
    const int wid  = tid >> 5;
    const int wm   = wid & 1;      // 2 M groups of 64
    const int wn   = wid >> 1;     // 4 N groups of 64

    // mbarriers: full[s] = sbase + s*16, empty[s] = sbase + s*16 + 8
    if (tid == 0) {
        #pragma unroll
        for (int s = 0; s < STAGES; s++) {
            mbar_init(sbase + s * 16,     256);  // full
            mbar_init(sbase + s * 16 + 8,   8);  // empty
        }
    }
    __syncthreads();

    const int m0 = (blockIdx.x / NT) * BM;
    const int n0 = (blockIdx.x % NT) * BN;

    const __half* Ag = g_xh + (size_t)m0 * KDIM;
    const __half* Bg = g_Wh + (size_t)n0 * KDIM;

    auto load_stage = [&](int kt, int slot) {
        const uint32_t sa = tiles + slot * STAGE_BYTES;
        const uint32_t sb = sa + A_BYTES;
        const __half* ga = Ag + kt * BK;
        const __half* gb = Bg + kt * BK;
        #pragma unroll
        for (int i = 0; i < 4; i++) {            // A: 1024 16B chunks
            int chunk = i * 256 + tid;
            int r = chunk >> 3, c = chunk & 7;
            uint32_t so = sa + r * 128 + ((c ^ (r & 7)) << 4);
            const __half* g = ga + (size_t)r * KDIM + c * 8;
            asm volatile("cp.async.cg.shared.global [%0], [%1], 16;" :: "r"(so), "l"(g));
        }
        #pragma unroll
        for (int i = 0; i < 8; i++) {            // B: 2048 16B chunks
            int chunk = i * 256 + tid;
            int r = chunk >> 3, c = chunk & 7;
            uint32_t so = sb + r * 128 + ((c ^ (r & 7)) << 4);
            const __half* g = gb + (size_t)r * KDIM + c * 8;
            asm volatile("cp.async.cg.shared.global [%0], [%1], 16;" :: "r"(so), "l"(g));
        }
        cpasync_mbar_arrive(sbase + slot * 16);  // full[slot], fires on completion
    };

    float acc[4][8][4];
    #pragma unroll
    for (int i = 0; i < 4; i++)
        #pragma unroll
        for (int j = 0; j < 8; j++)
            #pragma unroll
            for (int k = 0; k < 4; k++) acc[i][j][k] = 0.f;

    const int br_base = wn * 64 + ((lane >> 4) << 3) + (lane & 7);   // + q*16
    const int bc_sel  = (lane >> 3) & 1;                             // + 2*ks
    const int ar_base = wm * 64 + (lane & 15);                       // + mt*16
    const int ac_sel  = lane >> 4;                                   // + 2*ks

    auto compute_stage = [&](int slot) {
        const uint32_t sa = tiles + slot * STAGE_BYTES;
        const uint32_t sb = sa + A_BYTES;

        uint32_t bf[2][16];  // B frags (n64), double-buffered over ks
        uint32_t af[2][4];   // A frags, double-buffered over mt

        auto ldB = [&](int ks, uint32_t* dst) {
            #pragma unroll
            for (int q = 0; q < 4; q++) {
                int r = br_base + q * 16;
                int c = 2 * ks + bc_sel;
                uint32_t addr = sb + r * 128 + ((c ^ (r & 7)) << 4);
                asm volatile("ldmatrix.sync.aligned.m8n8.x4.shared.b16 {%0,%1,%2,%3}, [%4];"
                    : "=r"(dst[q*4+0]), "=r"(dst[q*4+1]), "=r"(dst[q*4+2]), "=r"(dst[q*4+3])
                    : "r"(addr));
            }
        };
        auto ldA = [&](int ks, int mt, uint32_t* dst) {
            int r = ar_base + mt * 16;
            int c = 2 * ks + ac_sel;
            uint32_t addr = sa + r * 128 + ((c ^ (r & 7)) << 4);
            asm volatile("ldmatrix.sync.aligned.m8n8.x4.shared.b16 {%0,%1,%2,%3}, [%4];"
                : "=r"(dst[0]), "=r"(dst[1]), "=r"(dst[2]), "=r"(dst[3])
                : "r"(addr));
        };

        ldB(0, bf[0]);
        ldA(0, 0, af[0]);

        #pragma unroll
        for (int ks = 0; ks < 4; ks++) {
            if (ks < 3) ldB(ks + 1, bf[(ks + 1) & 1]);
            const uint32_t* b = bf[ks & 1];
            #pragma unroll
            for (int mt = 0; mt < 4; mt++) {
                if (mt < 3)      ldA(ks,     mt + 1, af[(mt + 1) & 1]);
                else if (ks < 3) ldA(ks + 1, 0,      af[0]);
                const uint32_t* a = af[mt & 1];
                #pragma unroll
                for (int nt = 0; nt < 8; nt++) {
                    asm volatile(
                        "mma.sync.aligned.m16n8k16.row.col.f32.f16.f16.f32 "
                        "{%0,%1,%2,%3},{%4,%5,%6,%7},{%8,%9},{%0,%1,%2,%3};"
                        : "+f"(acc[mt][nt][0]), "+f"(acc[mt][nt][1]),
                          "+f"(acc[mt][nt][2]), "+f"(acc[mt][nt][3])
                        : "r"(a[0]), "r"(a[1]), "r"(a[2]), "r"(a[3]),
                          "r"(b[(nt >> 1) * 4 + (nt & 1) * 2]),
                          "r"(b[(nt >> 1) * 4 + (nt & 1) * 2 + 1]));
                }
            }
        }
    };

    // prologue: fill 3 of 4 stages
    load_stage(0, 0);
    load_stage(1, 1);
    load_stage(2, 2);

    for (int kt = 0; kt < KT; kt++) {
        const int ls = kt + 3;
        if (ls < KT) {
            const int s = ls & 3;
            if (ls >= STAGES)
                mbar_wait(sbase + s * 16 + 8, ((ls / STAGES) - 1) & 1);  // empty[s]
            load_stage(ls, s);
        }
        const int cs = kt & 3;
        mbar_wait(sbase + cs * 16, (kt / STAGES) & 1);                   // full[cs]
        compute_stage(cs);
        __syncwarp();
        if (lane == 0) mbar_arrive(sbase + cs * 16 + 8);                 // empty[cs]
    }

    // ---- epilogue ----
    const int g   = lane >> 2;
    const int tig = lane & 3;
    #pragma unroll
    for (int mt = 0; mt < 4; mt++) {
        const int row = m0 + wm * 64 + mt * 16 + g;
        #pragma unroll
        for (int nt = 0; nt < 8; nt++) {
            const int col = n0 + wn * 64 + nt * 8 + tig * 2;
            const float b0 = __ldg(bias + col), b1 = __ldg(bias + col + 1);
            float2 v0 = make_float2(acc[mt][nt][0] + b0, acc[mt][nt][1] + b1);
            float2 v1 = make_float2(acc[mt][nt][2] + b0, acc[mt][nt][3] + b1);
            *reinterpret_cast<float2*>(y + (size_t)row       * NDIM + col) = v0;
            *reinterpret_cast<float2*>(y + (size_t)(row + 8) * NDIM + col) = v1;
        }
    }
}

// ------------------------------------------------------------------- host ----
extern "C" void kernel_launch(void* const* d_in, const int* in_sizes, int n_in,
                              void* d_out, int out_size) {
    const float* x      = (const float*)d_in[0];
    const float* values = (const float*)d_in[1];
    const int*   col    = (const int*)d_in[2];
    const float* bias   = (const float*)d_in[3];
    float* y = (float*)d_out;

    prep_kernel<<<NDIM + CVT_BLOCKS, 256>>>(values, col, (const float4*)x);

    static bool attr_set = false;
    if (!attr_set) {
        cudaFuncSetAttribute(gemm_kernel, cudaFuncAttributeMaxDynamicSharedMemorySize, SMEM_SIZE);
        attr_set = true;
    }
    gemm_kernel<<<MT * NT, 256, SMEM_SIZE>>>(bias, y);
}